// round 12
// baseline (speedup 1.0000x reference)
#include <cuda_runtime.h>
#include <cstdint>

// ===========================================================================
// OctreeGnResBlock2: mma.sync tf32, ldmatrix fragments, 256-node tiles.
// A-gather: depth-3 cp.async pipeline (2-stage lookahead); W: depth-2 in
// separate commit groups. wait_group 1 per iteration. 2 CTAs/SM.
//   kA : g_h = relu(GN_a(sum_k gather(x) @ Wa[k]))        27 K=32 stages
//   kB : out = relu(GN_b(sum_k gather(h) @ Wb[k]) + GN_s(x @ W1))
//        54 K=32 half-tap stages + folded shortcut stage
// CTA = 256 nodes / 256 thr; 8 warps = 4(m64) x 2(n32).
// smem/CTA: A0,A1,A2 (3x32KB) + W0,W1 (2x8KB) = 112KB.
// ===========================================================================

__device__ float g_h  [800000ULL * 64];
__device__ float g_xt [800000ULL * 32];
__device__ float g_Wat[27 * 64 * 32];    // [k][cout][cin] tf32
__device__ float g_Wbt[27 * 64 * 64];
__device__ float g_W1t[64 * 32];

__device__ __forceinline__ float totf32(float f) {
    uint32_t u;
    asm("cvt.rna.tf32.f32 %0, %1;" : "=r"(u) : "f"(f));
    return __uint_as_float(u);
}
__device__ __forceinline__ uint32_t s2u(const void* p) {
    uint32_t a;
    asm("{ .reg .u64 t; cvta.to.shared.u64 t, %1; cvt.u32.u64 %0, t; }"
        : "=r"(a) : "l"(p));
    return a;
}
__device__ __forceinline__ void cpa16(uint32_t d, const void* s) {
    asm volatile("cp.async.cg.shared.global [%0], [%1], 16;" :: "r"(d), "l"(s));
}
#define CPA_COMMIT() asm volatile("cp.async.commit_group;" ::: "memory")
#define CPA_WAIT(N)  asm volatile("cp.async.wait_group %0;" :: "n"(N) : "memory")

#define LDSM4(d0, d1, d2, d3, addr)                                          \
    asm volatile("ldmatrix.sync.aligned.m8n8.x4.shared.b16 {%0,%1,%2,%3}, [%4];" \
                 : "=r"(d0), "=r"(d1), "=r"(d2), "=r"(d3) : "r"(addr))

#define MMA(c, a, b0, b1)                                                    \
    asm volatile(                                                            \
        "mma.sync.aligned.m16n8k8.row.col.f32.tf32.tf32.f32 "                \
        "{%0,%1,%2,%3},{%4,%5,%6,%7},{%8,%9},{%0,%1,%2,%3};"                 \
        : "+f"((c)[0]), "+f"((c)[1]), "+f"((c)[2]), "+f"((c)[3])             \
        : "r"((a)[0]), "r"((a)[1]), "r"((a)[2]), "r"((a)[3]),                \
          "r"(b0), "r"(b1))

struct Frag {
    uint32_t pA, pB, rxA, rxB;
    int g, t, mb, nb;
};
__device__ __forceinline__ Frag mkfrag(int wid, int lid) {
    Frag f;
    const uint32_t r = lid & 7, h8 = (lid >> 3) & 1, kp = (uint32_t)lid >> 4;
    const uint32_t q = (uint32_t)lid >> 3;
    const int warpM = wid & 3, warpN = wid >> 2;
    f.pA  = (warpM * 64 + h8 * 8 + r) * 128u;
    f.rxA = kp ^ r;
    f.pB  = (warpN * 32 + (q >> 1) * 8 + r) * 128u;
    f.rxB = (q & 1) ^ r;
    f.g = lid >> 2; f.t = lid & 3;
    f.mb = warpM * 64; f.nb = warpN * 32;
    return f;
}

// one K=32 stage: A[256x32] @ W[64x32]^T, warp tile m64n32
__device__ __forceinline__ void mma_stage(uint32_t aSt, uint32_t wSt,
                                          float c[4][4][4], const Frag& f) {
#pragma unroll
    for (uint32_t s = 0; s < 4; ++s) {
        uint32_t a[4][4];
#pragma unroll
        for (int mi = 0; mi < 4; ++mi)
            LDSM4(a[mi][0], a[mi][1], a[mi][2], a[mi][3],
                  aSt + f.pA + mi * 2048u + (((2u * s) ^ f.rxA) << 4));
        uint32_t b[2][4];
#pragma unroll
        for (int j = 0; j < 2; ++j)
            LDSM4(b[j][0], b[j][1], b[j][2], b[j][3],
                  wSt + f.pB + j * 2048u + (((2u * s) ^ f.rxB) << 4));
#pragma unroll
        for (int mi = 0; mi < 4; ++mi) {
            MMA(c[mi][0], a[mi], b[0][0], b[0][1]);
            MMA(c[mi][1], a[mi], b[0][2], b[0][3]);
            MMA(c[mi][2], a[mi], b[1][0], b[1][1]);
            MMA(c[mi][3], a[mi], b[1][2], b[1][3]);
        }
    }
}

// ---------------- prep ----------------
__global__ void k_prepW(const float* __restrict__ Wa,
                        const float* __restrict__ Wb,
                        const float* __restrict__ W1) {
    const int t = blockIdx.x * 256 + threadIdx.x;
    if (t < 27 * 64 * 32) {
        const int k = t / 2048, o = (t % 2048) / 32, i = t % 32;
        g_Wat[t] = totf32(Wa[k * 2048 + i * 64 + o]);
    }
    if (t < 27 * 64 * 64) {
        const int k = t / 4096, o = (t % 4096) / 64, i = t % 64;
        g_Wbt[t] = totf32(Wb[k * 4096 + i * 64 + o]);
    }
    if (t < 2048) {
        const int o = t / 32, i = t % 32;
        g_W1t[t] = totf32(W1[i * 64 + o]);
    }
}
__global__ void k_prepX(const float* __restrict__ x, long long n32) {
    for (long long i = blockIdx.x * 256LL + threadIdx.x; i < n32;
         i += (long long)gridDim.x * 256)
        g_xt[i] = totf32(x[i]);
}

static constexpr int STA  = 32768;          // one A stage
static constexpr uint32_t WOFF = 98304;     // W buffers after 3 A stages
static constexpr int WSTG = 8192;           // one W stage
static constexpr int SMB  = 114688;         // 3*32KB + 2*8KB

// ---------------- kA: 27 K=32 taps -> g_h ----------------
__global__ void __launch_bounds__(256, 2) kA(
    const int* __restrict__ neigh, const float* __restrict__ gw,
    const float* __restrict__ gb, int n)
{
    extern __shared__ char smem[];
    const uint32_t sb = s2u(smem);
    const int tid = threadIdx.x, wid = tid >> 5, lid = tid & 31;
    const int tile = blockIdx.x;
    const int rows = min(256, n - tile * 256);

    int lrow = 4 * wid + (lid & 3) + 32 * (lid >> 2);
    if (lrow >= rows) lrow = 0;
    const int* nsrc = neigh + ((long long)tile * 256 + lrow) * 27;
    const int slq = lid >> 3;

    const int seg = tid & 7, r0 = tid >> 3;
    const uint32_t sw16 = (uint32_t)(seg ^ (r0 & 7)) * 16u;
    const uint32_t aDst = sb + (uint32_t)r0 * 128u + sw16;
    const uint32_t wDst = sb + WOFF + (uint32_t)r0 * 128u + sw16;
    const float* wsrc = g_Wat + r0 * 32 + seg * 4;

    float c[4][4][4];
#pragma unroll
    for (int mi = 0; mi < 4; ++mi)
#pragma unroll
        for (int nn = 0; nn < 4; ++nn)
#pragma unroll
            for (int j = 0; j < 4; ++j) c[mi][nn][j] = 0.f;

    auto stageA = [&](int k, uint32_t so) {
        const int v = __ldg(nsrc + k);
#pragma unroll
        for (int q = 0; q < 8; ++q) {
            const long long idx = __shfl_sync(0xffffffffu, v, 4 * q + slq);
            cpa16(aDst + so + q * 4096u, g_xt + idx * 32 + seg * 4);
        }
        CPA_COMMIT();
    };
    auto stageW = [&](int k, uint32_t so) {
        cpa16(wDst + so, wsrc + k * 2048);
        cpa16(wDst + so + 4096u, wsrc + k * 2048 + 1024);
        CPA_COMMIT();
    };

    const Frag f = mkfrag(wid, lid);
    stageW(0, 0u); stageA(0, 0u); stageA(1, (uint32_t)STA);
    uint32_t soC = 0u, soP = 2u * STA;
#pragma unroll 1
    for (int k = 0; k < 27; ++k) {
        CPA_WAIT(1);
        __syncthreads();
        if (k + 1 < 27) stageW(k + 1, (uint32_t)((k + 1) & 1) * WSTG);
        else CPA_COMMIT();
        if (k + 2 < 27) stageA(k + 2, soP);
        else CPA_COMMIT();
        mma_stage(sb + soC, sb + WOFF + (uint32_t)(k & 1) * WSTG, c, f);
        soC = (soC == 2u * STA) ? 0u : soC + STA;
        soP = (soP == 2u * STA) ? 0u : soP + STA;
    }

#pragma unroll
    for (int mi = 0; mi < 4; ++mi)
#pragma unroll
        for (int h = 0; h < 2; ++h) {
            const int row = f.mb + mi * 16 + f.g + 8 * h;
#pragma unroll
            for (int nn = 0; nn < 4; ++nn) {
                const float v0 = c[mi][nn][2 * h], v1 = c[mi][nn][2 * h + 1];
                float s = v0 + v1;
                s += __shfl_xor_sync(0xffffffffu, s, 1);
                const float mu = s * 0.25f;
                const float d0 = v0 - mu, d1 = v1 - mu;
                float qv = d0 * d0 + d1 * d1;
                qv += __shfl_xor_sync(0xffffffffu, qv, 1);
                const float rs = rsqrtf(qv * 0.25f + 1e-5f);
                const int col = f.nb + nn * 8 + f.t * 2;
                if (row < rows) {
                    float2 o;
                    o.x = totf32(fmaxf(fmaf(d0 * rs, __ldg(gw + col),
                                            __ldg(gb + col)), 0.f));
                    o.y = totf32(fmaxf(fmaf(d1 * rs, __ldg(gw + col + 1),
                                            __ldg(gb + col + 1)), 0.f));
                    *(float2*)(g_h + ((long long)tile * 256 + row) * 64 + col) = o;
                }
            }
        }
}

// ---------------- kB: 54 half-taps + folded shortcut ----------------
__global__ void __launch_bounds__(256, 2) kB(
    const int* __restrict__ neigh,
    const float* __restrict__ gbw, const float* __restrict__ gbb,
    const float* __restrict__ gsw, const float* __restrict__ gsb,
    float* __restrict__ out, int n)
{
    extern __shared__ char smem[];
    const uint32_t sb = s2u(smem);
    const int tid = threadIdx.x, wid = tid >> 5, lid = tid & 31;
    const int tile = blockIdx.x;
    const int rows = min(256, n - tile * 256);

    int lrow = 4 * wid + (lid & 3) + 32 * (lid >> 2);
    if (lrow >= rows) lrow = 0;
    const int* nsrc = neigh + ((long long)tile * 256 + lrow) * 27;
    const int slq = lid >> 3;

    const int seg = tid & 7, r0 = tid >> 3;
    const uint32_t sw16 = (uint32_t)(seg ^ (r0 & 7)) * 16u;
    const uint32_t aDst = sb + (uint32_t)r0 * 128u + sw16;
    const uint32_t wDst = sb + WOFF + (uint32_t)r0 * 128u + sw16;
    const float* wsrc = g_Wbt + r0 * 64 + seg * 4;

    float c[4][4][4];
#pragma unroll
    for (int mi = 0; mi < 4; ++mi)
#pragma unroll
        for (int nn = 0; nn < 4; ++nn)
#pragma unroll
            for (int j = 0; j < 4; ++j) c[mi][nn][j] = 0.f;

    auto stageA = [&](int s, uint32_t so) {
        const int k = s >> 1, hf = (s & 1) * 32;
        const int v = __ldg(nsrc + k);
#pragma unroll
        for (int q = 0; q < 8; ++q) {
            const long long idx = __shfl_sync(0xffffffffu, v, 4 * q + slq);
            cpa16(aDst + so + q * 4096u, g_h + idx * 64 + hf + seg * 4);
        }
        CPA_COMMIT();
    };
    auto stageW = [&](int s, uint32_t so) {
        const int k = s >> 1, hf = (s & 1) * 32;
        cpa16(wDst + so, wsrc + k * 4096 + hf);
        cpa16(wDst + so + 4096u, wsrc + k * 4096 + hf + 2048);
        CPA_COMMIT();
    };

    const Frag f = mkfrag(wid, lid);
    stageW(0, 0u); stageA(0, 0u); stageA(1, (uint32_t)STA);
    uint32_t soC = 0u, soP = 2u * STA;
#pragma unroll 1
    for (int s = 0; s < 54; ++s) {
        CPA_WAIT(1);
        __syncthreads();
        if (s + 1 < 54) stageW(s + 1, (uint32_t)((s + 1) & 1) * WSTG);
        else CPA_COMMIT();
        if (s + 2 < 54) stageA(s + 2, soP);
        else CPA_COMMIT();
        mma_stage(sb + soC, sb + WOFF + (uint32_t)(s & 1) * WSTG, c, f);
        soC = (soC == 2u * STA) ? 0u : soC + STA;
        soP = (soP == 2u * STA) ? 0u : soP + STA;
    }
    CPA_WAIT(0);
    __syncthreads();   // all stage-buffer reads complete everywhere

    // ---- shortcut gather: A into A2 (65536), W1 into W0 (98304) ----
    {
        const uint32_t scA = sb + 65536u;
#pragma unroll
        for (int q = 0; q < 8; ++q) {
            const int row = r0 + 32 * q;
            const long long nd = (long long)tile * 256 + ((row < rows) ? row : 0);
            cpa16(scA + (uint32_t)row * 128u + sw16, g_xt + nd * 32 + seg * 4);
        }
        cpa16(sb + WOFF + (uint32_t)r0 * 128u + sw16, g_W1t + r0 * 32 + seg * 4);
        cpa16(sb + WOFF + 4096u + (uint32_t)r0 * 128u + sw16,
              g_W1t + (r0 + 32) * 32 + seg * 4);
        CPA_COMMIT();
    }

    // ---- phase 1: GN_b -> smem conv buffer (overlays A0+A1) ----
    float* convBuf = (float*)smem;   // 256*64 f = 64KB
#pragma unroll
    for (int mi = 0; mi < 4; ++mi)
#pragma unroll
        for (int h = 0; h < 2; ++h) {
            const int row = f.mb + mi * 16 + f.g + 8 * h;
#pragma unroll
            for (int nn = 0; nn < 4; ++nn) {
                const float v0 = c[mi][nn][2 * h], v1 = c[mi][nn][2 * h + 1];
                float s = v0 + v1;
                s += __shfl_xor_sync(0xffffffffu, s, 1);
                const float mub = s * 0.25f;
                const float d0 = v0 - mub, d1 = v1 - mub;
                float qv = d0 * d0 + d1 * d1;
                qv += __shfl_xor_sync(0xffffffffu, qv, 1);
                const float rb = rsqrtf(qv * 0.25f + 1e-5f);
                const int col = f.nb + nn * 8 + f.t * 2;
                convBuf[row * 64 + col]     =
                    fmaf(d0 * rb, __ldg(gbw + col), __ldg(gbb + col));
                convBuf[row * 64 + col + 1] =
                    fmaf(d1 * rb, __ldg(gbw + col + 1), __ldg(gbb + col + 1));
            }
        }

#pragma unroll
    for (int mi = 0; mi < 4; ++mi)
#pragma unroll
        for (int nn = 0; nn < 4; ++nn)
#pragma unroll
            for (int j = 0; j < 4; ++j) c[mi][nn][j] = 0.f;

    CPA_WAIT(0);
    __syncthreads();   // convBuf visible + shortcut stage loaded
    mma_stage(sb + 65536u, sb + WOFF, c, f);

    // ---- phase 2: GN_s + add + ReLU -> out ----
#pragma unroll
    for (int mi = 0; mi < 4; ++mi)
#pragma unroll
        for (int h = 0; h < 2; ++h) {
            const int row = f.mb + mi * 16 + f.g + 8 * h;
#pragma unroll
            for (int nn = 0; nn < 4; ++nn) {
                const float v0 = c[mi][nn][2 * h], v1 = c[mi][nn][2 * h + 1];
                float s = v0 + v1;
                s += __shfl_xor_sync(0xffffffffu, s, 1);
                const float mus = s * 0.25f;
                const float e0 = v0 - mus, e1 = v1 - mus;
                float qv = e0 * e0 + e1 * e1;
                qv += __shfl_xor_sync(0xffffffffu, qv, 1);
                const float rss = rsqrtf(qv * 0.25f + 1e-5f);
                const int col = f.nb + nn * 8 + f.t * 2;
                if (row < rows) {
                    const float cv0 = convBuf[row * 64 + col];
                    const float cv1 = convBuf[row * 64 + col + 1];
                    float2 o;
                    o.x = fmaxf(cv0 + fmaf(e0 * rss, __ldg(gsw + col),
                                           __ldg(gsb + col)), 0.f);
                    o.y = fmaxf(cv1 + fmaf(e1 * rss, __ldg(gsw + col + 1),
                                           __ldg(gsb + col + 1)), 0.f);
                    *(float2*)(out + ((long long)tile * 256 + row) * 64 + col) = o;
                }
            }
        }
}

// ---------------------------------------------------------------------------
extern "C" void kernel_launch(void* const* d_in, const int* in_sizes, int n_in,
                              void* d_out, int out_size) {
    const float* data  = (const float*)d_in[0];
    const int*   neigh = (const int*)d_in[1];
    const float* Wa    = (const float*)d_in[2];
    const float* ga_w  = (const float*)d_in[3];
    const float* ga_b  = (const float*)d_in[4];
    const float* Wb    = (const float*)d_in[5];
    const float* gb_w  = (const float*)d_in[6];
    const float* gb_b  = (const float*)d_in[7];
    const float* W1    = (const float*)d_in[8];
    const float* gs_w  = (const float*)d_in[9];
    const float* gs_b  = (const float*)d_in[10];
    float* out = (float*)d_out;

    const int n = in_sizes[0] / 32;
    const int tiles = (n + 255) / 256;

    cudaFuncSetAttribute(kA, cudaFuncAttributeMaxDynamicSharedMemorySize, SMB);
    cudaFuncSetAttribute(kB, cudaFuncAttributeMaxDynamicSharedMemorySize, SMB);

    k_prepW<<<(27 * 64 * 64 + 255) / 256, 256>>>(Wa, Wb, W1);
    k_prepX<<<2048, 256>>>(data, (long long)n * 32);
    kA<<<tiles, 256, SMB>>>(neigh, ga_w, ga_b, n);
    kB<<<tiles, 256, SMB>>>(neigh, gb_w, gb_b, gs_w, gs_b, out, n);
}

// round 13
// speedup vs baseline: 1.0998x; 1.0998x over previous
#include <cuda_runtime.h>
#include <cstdint>

// ===========================================================================
// OctreeGnResBlock2: mma.sync tf32, ldmatrix fragments, 128-node tiles,
// 4 CTAs/SM (128 thr, 4 warps = 2(m64) x 2(n32)), depth-2 cp.async stages.
//   kA : g_h = relu(GN_a(sum_k gather(x) @ Wa[k]))        27 K=32 stages
//   kB : out = relu(GN_b(sum_k gather(h) @ Wb[k]) + GN_s(x @ W1))
//        54 K=32 half-tap stages; shortcut via out-gmem two-phase epilogue
// Stage = A 16KB + W 8KB = 24KB; 2 stages = 48KB/CTA -> 4 CTAs/SM.
// ===========================================================================

__device__ float g_h  [800000ULL * 64];
__device__ float g_xt [800000ULL * 32];
__device__ float g_Wat[27 * 64 * 32];    // [k][cout][cin] tf32
__device__ float g_Wbt[27 * 64 * 64];
__device__ float g_W1t[64 * 32];

__device__ __forceinline__ float totf32(float f) {
    uint32_t u;
    asm("cvt.rna.tf32.f32 %0, %1;" : "=r"(u) : "f"(f));
    return __uint_as_float(u);
}
__device__ __forceinline__ uint32_t s2u(const void* p) {
    uint32_t a;
    asm("{ .reg .u64 t; cvta.to.shared.u64 t, %1; cvt.u32.u64 %0, t; }"
        : "=r"(a) : "l"(p));
    return a;
}
__device__ __forceinline__ void cpa16(uint32_t d, const void* s) {
    asm volatile("cp.async.cg.shared.global [%0], [%1], 16;" :: "r"(d), "l"(s));
}
#define CPA_COMMIT() asm volatile("cp.async.commit_group;" ::: "memory")
#define CPA_WAIT0()  asm volatile("cp.async.wait_group 0;"  ::: "memory")

#define LDSM4(d0, d1, d2, d3, addr)                                          \
    asm volatile("ldmatrix.sync.aligned.m8n8.x4.shared.b16 {%0,%1,%2,%3}, [%4];" \
                 : "=r"(d0), "=r"(d1), "=r"(d2), "=r"(d3) : "r"(addr))

#define MMA(c, a, b0, b1)                                                    \
    asm volatile(                                                            \
        "mma.sync.aligned.m16n8k8.row.col.f32.tf32.tf32.f32 "                \
        "{%0,%1,%2,%3},{%4,%5,%6,%7},{%8,%9},{%0,%1,%2,%3};"                 \
        : "+f"((c)[0]), "+f"((c)[1]), "+f"((c)[2]), "+f"((c)[3])             \
        : "r"((a)[0]), "r"((a)[1]), "r"((a)[2]), "r"((a)[3]),                \
          "r"(b0), "r"(b1))

struct Frag {
    uint32_t pA, pB, rxA, rxB;
    int g, t, mb, nb;
};
__device__ __forceinline__ Frag mkfrag(int wid, int lid) {
    Frag f;
    const uint32_t r = lid & 7, h8 = (lid >> 3) & 1, kp = (uint32_t)lid >> 4;
    const uint32_t q = (uint32_t)lid >> 3;
    const int warpM = wid & 1, warpN = wid >> 1;
    f.pA  = (warpM * 64 + h8 * 8 + r) * 128u;
    f.rxA = kp ^ r;
    f.pB  = (warpN * 32 + (q >> 1) * 8 + r) * 128u;
    f.rxB = (q & 1) ^ r;
    f.g = lid >> 2; f.t = lid & 3;
    f.mb = warpM * 64; f.nb = warpN * 32;
    return f;
}

// one K=32 stage: A[128x32] @ W[64x32]^T, warp tile m64n32; W at A+16KB
__device__ __forceinline__ void mma_stage(uint32_t aSt, float c[4][4][4],
                                          const Frag& f) {
    const uint32_t wSt = aSt + 16384u;
#pragma unroll
    for (uint32_t s = 0; s < 4; ++s) {
        uint32_t a[4][4];
#pragma unroll
        for (int mi = 0; mi < 4; ++mi)
            LDSM4(a[mi][0], a[mi][1], a[mi][2], a[mi][3],
                  aSt + f.pA + mi * 2048u + (((2u * s) ^ f.rxA) << 4));
        uint32_t b[2][4];
#pragma unroll
        for (int j = 0; j < 2; ++j)
            LDSM4(b[j][0], b[j][1], b[j][2], b[j][3],
                  wSt + f.pB + j * 2048u + (((2u * s) ^ f.rxB) << 4));
#pragma unroll
        for (int mi = 0; mi < 4; ++mi) {
            MMA(c[mi][0], a[mi], b[0][0], b[0][1]);
            MMA(c[mi][1], a[mi], b[0][2], b[0][3]);
            MMA(c[mi][2], a[mi], b[1][0], b[1][1]);
            MMA(c[mi][3], a[mi], b[1][2], b[1][3]);
        }
    }
}

// ---------------- prep ----------------
__global__ void k_prepW(const float* __restrict__ Wa,
                        const float* __restrict__ Wb,
                        const float* __restrict__ W1) {
    const int t = blockIdx.x * 256 + threadIdx.x;
    if (t < 27 * 64 * 32) {
        const int k = t / 2048, o = (t % 2048) / 32, i = t % 32;
        g_Wat[t] = totf32(Wa[k * 2048 + i * 64 + o]);
    }
    if (t < 27 * 64 * 64) {
        const int k = t / 4096, o = (t % 4096) / 64, i = t % 64;
        g_Wbt[t] = totf32(Wb[k * 4096 + i * 64 + o]);
    }
    if (t < 2048) {
        const int o = t / 32, i = t % 32;
        g_W1t[t] = totf32(W1[i * 64 + o]);
    }
}
__global__ void k_prepX(const float* __restrict__ x, long long n32) {
    for (long long i = blockIdx.x * 256LL + threadIdx.x; i < n32;
         i += (long long)gridDim.x * 256)
        g_xt[i] = totf32(x[i]);
}

static constexpr int STG = 24576;           // A 16KB + W 8KB
static constexpr int SMB = 2 * STG;         // 49152 -> 4 CTAs/SM

// ---------------- kA: 27 K=32 taps -> g_h ----------------
__global__ void __launch_bounds__(128, 4) kA(
    const int* __restrict__ neigh, const float* __restrict__ gw,
    const float* __restrict__ gb, int n)
{
    extern __shared__ char smem[];
    const uint32_t sb = s2u(smem);
    const int tid = threadIdx.x, wid = tid >> 5, lid = tid & 31;
    const int tile = blockIdx.x;
    const int rows = min(128, n - tile * 128);

    // lane l of warp w owns gather row 4w + (l&3) + 16*(l>>2)
    int lrow = 4 * wid + (lid & 3) + 16 * (lid >> 2);
    if (lrow >= rows) lrow = 0;
    const int* nsrc = neigh + ((long long)tile * 128 + lrow) * 27;
    const int slq = lid >> 3;                   // 0..3

    const int seg = tid & 7, r0 = tid >> 3;     // r0 0..15
    const uint32_t sw16 = (uint32_t)(seg ^ (r0 & 7)) * 16u;
    const uint32_t aDst = sb + (uint32_t)r0 * 128u + sw16;
    const uint32_t wDst = sb + 16384u + (uint32_t)r0 * 128u + sw16;
    const float* wsrc = g_Wat + r0 * 32 + seg * 4;

    float c[4][4][4];
#pragma unroll
    for (int mi = 0; mi < 4; ++mi)
#pragma unroll
        for (int nn = 0; nn < 4; ++nn)
#pragma unroll
            for (int j = 0; j < 4; ++j) c[mi][nn][j] = 0.f;

    auto stage = [&](int k, uint32_t so) {
        const int v = __ldg(nsrc + k);
#pragma unroll
        for (int q = 0; q < 8; ++q) {           // rows r0 + 16q
            const long long idx = __shfl_sync(0xffffffffu, v, 4 * q + slq);
            cpa16(aDst + so + q * 2048u, g_xt + idx * 32 + seg * 4);
        }
#pragma unroll
        for (int j = 0; j < 4; ++j)             // W rows r0 + 16j
            cpa16(wDst + so + j * 2048u, wsrc + k * 2048 + j * 512);
        CPA_COMMIT();
    };

    const Frag f = mkfrag(wid, lid);
    stage(0, 0u);
#pragma unroll 1
    for (int k = 0; k < 27; ++k) {
        const uint32_t so = (k & 1) ? (uint32_t)STG : 0u;
        CPA_WAIT0();
        __syncthreads();
        if (k + 1 < 27) stage(k + 1, so ^ (uint32_t)STG);
        mma_stage(sb + so, c, f);
    }

#pragma unroll
    for (int mi = 0; mi < 4; ++mi)
#pragma unroll
        for (int h = 0; h < 2; ++h) {
            const int row = f.mb + mi * 16 + f.g + 8 * h;
#pragma unroll
            for (int nn = 0; nn < 4; ++nn) {
                const float v0 = c[mi][nn][2 * h], v1 = c[mi][nn][2 * h + 1];
                float s = v0 + v1;
                s += __shfl_xor_sync(0xffffffffu, s, 1);
                const float mu = s * 0.25f;
                const float d0 = v0 - mu, d1 = v1 - mu;
                float qv = d0 * d0 + d1 * d1;
                qv += __shfl_xor_sync(0xffffffffu, qv, 1);
                const float rs = rsqrtf(qv * 0.25f + 1e-5f);
                const int col = f.nb + nn * 8 + f.t * 2;
                if (row < rows) {
                    float2 o;
                    o.x = totf32(fmaxf(fmaf(d0 * rs, __ldg(gw + col),
                                            __ldg(gb + col)), 0.f));
                    o.y = totf32(fmaxf(fmaf(d1 * rs, __ldg(gw + col + 1),
                                            __ldg(gb + col + 1)), 0.f));
                    *(float2*)(g_h + ((long long)tile * 128 + row) * 64 + col) = o;
                }
            }
        }
}

// ---------------- kB: 54 half-taps + shortcut via out round-trip ----------
__global__ void __launch_bounds__(128, 4) kB(
    const int* __restrict__ neigh,
    const float* __restrict__ gbw, const float* __restrict__ gbb,
    const float* __restrict__ gsw, const float* __restrict__ gsb,
    float* __restrict__ out, int n)
{
    extern __shared__ char smem[];
    const uint32_t sb = s2u(smem);
    const int tid = threadIdx.x, wid = tid >> 5, lid = tid & 31;
    const int tile = blockIdx.x;
    const int rows = min(128, n - tile * 128);

    int lrow = 4 * wid + (lid & 3) + 16 * (lid >> 2);
    if (lrow >= rows) lrow = 0;
    const int* nsrc = neigh + ((long long)tile * 128 + lrow) * 27;
    const int slq = lid >> 3;

    const int seg = tid & 7, r0 = tid >> 3;
    const uint32_t sw16 = (uint32_t)(seg ^ (r0 & 7)) * 16u;
    const uint32_t aDst = sb + (uint32_t)r0 * 128u + sw16;
    const uint32_t wDst = sb + 16384u + (uint32_t)r0 * 128u + sw16;
    const float* wsrc = g_Wbt + r0 * 64 + seg * 4;

    float c[4][4][4];
#pragma unroll
    for (int mi = 0; mi < 4; ++mi)
#pragma unroll
        for (int nn = 0; nn < 4; ++nn)
#pragma unroll
            for (int j = 0; j < 4; ++j) c[mi][nn][j] = 0.f;

    auto stage = [&](int s, uint32_t so) {
        const int k = s >> 1, hf = (s & 1) * 32;
        const int v = __ldg(nsrc + k);
#pragma unroll
        for (int q = 0; q < 8; ++q) {
            const long long idx = __shfl_sync(0xffffffffu, v, 4 * q + slq);
            cpa16(aDst + so + q * 2048u, g_h + idx * 64 + hf + seg * 4);
        }
#pragma unroll
        for (int j = 0; j < 4; ++j)
            cpa16(wDst + so + j * 2048u, wsrc + k * 4096 + hf + j * 1024);
        CPA_COMMIT();
    };

    const Frag f = mkfrag(wid, lid);
    stage(0, 0u);
#pragma unroll 1
    for (int s = 0; s < 54; ++s) {
        const uint32_t so = (s & 1) ? (uint32_t)STG : 0u;
        CPA_WAIT0();
        __syncthreads();
        if (s + 1 < 54) stage(s + 1, so ^ (uint32_t)STG);
        mma_stage(sb + so, c, f);
    }
    CPA_WAIT0();
    __syncthreads();   // all stage-buffer reads complete everywhere

    // ---- shortcut gather into buf0 (A @0, W1 @16384) ----
    {
#pragma unroll
        for (int q = 0; q < 8; ++q) {
            const int row = r0 + 16 * q;
            const long long nd = (long long)tile * 128 + ((row < rows) ? row : 0);
            cpa16(aDst + q * 2048u, g_xt + nd * 32 + seg * 4);
        }
#pragma unroll
        for (int j = 0; j < 4; ++j)
            cpa16(wDst + j * 2048u, g_W1t + r0 * 32 + seg * 4 + j * 512);
        CPA_COMMIT();
    }

    // ---- phase 1: GN_b -> out (gmem; re-read in phase 2 by same thread) ----
#pragma unroll
    for (int mi = 0; mi < 4; ++mi)
#pragma unroll
        for (int h = 0; h < 2; ++h) {
            const int row = f.mb + mi * 16 + f.g + 8 * h;
#pragma unroll
            for (int nn = 0; nn < 4; ++nn) {
                const float v0 = c[mi][nn][2 * h], v1 = c[mi][nn][2 * h + 1];
                float s = v0 + v1;
                s += __shfl_xor_sync(0xffffffffu, s, 1);
                const float mub = s * 0.25f;
                const float d0 = v0 - mub, d1 = v1 - mub;
                float qv = d0 * d0 + d1 * d1;
                qv += __shfl_xor_sync(0xffffffffu, qv, 1);
                const float rb = rsqrtf(qv * 0.25f + 1e-5f);
                const int col = f.nb + nn * 8 + f.t * 2;
                if (row < rows) {
                    float2 o;
                    o.x = fmaf(d0 * rb, __ldg(gbw + col), __ldg(gbb + col));
                    o.y = fmaf(d1 * rb, __ldg(gbw + col + 1), __ldg(gbb + col + 1));
                    *(float2*)(out + ((long long)tile * 128 + row) * 64 + col) = o;
                }
            }
        }

#pragma unroll
    for (int mi = 0; mi < 4; ++mi)
#pragma unroll
        for (int nn = 0; nn < 4; ++nn)
#pragma unroll
            for (int j = 0; j < 4; ++j) c[mi][nn][j] = 0.f;

    CPA_WAIT0();
    __syncthreads();   // shortcut stage loaded
    mma_stage(sb, c, f);

    // ---- phase 2: GN_s + add + ReLU -> out ----
#pragma unroll
    for (int mi = 0; mi < 4; ++mi)
#pragma unroll
        for (int h = 0; h < 2; ++h) {
            const int row = f.mb + mi * 16 + f.g + 8 * h;
#pragma unroll
            for (int nn = 0; nn < 4; ++nn) {
                const float v0 = c[mi][nn][2 * h], v1 = c[mi][nn][2 * h + 1];
                float s = v0 + v1;
                s += __shfl_xor_sync(0xffffffffu, s, 1);
                const float mus = s * 0.25f;
                const float e0 = v0 - mus, e1 = v1 - mus;
                float qv = e0 * e0 + e1 * e1;
                qv += __shfl_xor_sync(0xffffffffu, qv, 1);
                const float rss = rsqrtf(qv * 0.25f + 1e-5f);
                const int col = f.nb + nn * 8 + f.t * 2;
                if (row < rows) {
                    const long long base = ((long long)tile * 128 + row) * 64 + col;
                    const float2 cv = *(float2*)(out + base);   // same thread wrote it
                    float2 o;
                    o.x = fmaxf(cv.x + fmaf(e0 * rss, __ldg(gsw + col),
                                            __ldg(gsb + col)), 0.f);
                    o.y = fmaxf(cv.y + fmaf(e1 * rss, __ldg(gsw + col + 1),
                                            __ldg(gsb + col + 1)), 0.f);
                    *(float2*)(out + base) = o;
                }
            }
        }
}

// ---------------------------------------------------------------------------
extern "C" void kernel_launch(void* const* d_in, const int* in_sizes, int n_in,
                              void* d_out, int out_size) {
    const float* data  = (const float*)d_in[0];
    const int*   neigh = (const int*)d_in[1];
    const float* Wa    = (const float*)d_in[2];
    const float* ga_w  = (const float*)d_in[3];
    const float* ga_b  = (const float*)d_in[4];
    const float* Wb    = (const float*)d_in[5];
    const float* gb_w  = (const float*)d_in[6];
    const float* gb_b  = (const float*)d_in[7];
    const float* W1    = (const float*)d_in[8];
    const float* gs_w  = (const float*)d_in[9];
    const float* gs_b  = (const float*)d_in[10];
    float* out = (float*)d_out;

    const int n = in_sizes[0] / 32;
    const int tiles = (n + 127) / 128;

    cudaFuncSetAttribute(kA, cudaFuncAttributeMaxDynamicSharedMemorySize, SMB);
    cudaFuncSetAttribute(kB, cudaFuncAttributeMaxDynamicSharedMemorySize, SMB);

    k_prepW<<<(27 * 64 * 64 + 255) / 256, 256>>>(Wa, Wb, W1);
    k_prepX<<<2048, 256>>>(data, (long long)n * 32);
    kA<<<tiles, 128, SMB>>>(neigh, ga_w, ga_b, n);
    kB<<<tiles, 128, SMB>>>(neigh, gb_w, gb_b, gs_w, gs_b, out, n);
}